// round 1
// baseline (speedup 1.0000x reference)
#include <cuda_runtime.h>

#define EMBED 1024
#define BATCH 4
#define SEQ   2048
#define MTOT  (BATCH * SEQ)   // 8192

#define BM 128
#define BN 128
#define BK 8
#define TM 8
#define TN 8
#define NTHREADS 256

// Scratch for Q, K, V projections (device globals: no allocation in kernel_launch)
__device__ float g_Q[(size_t)MTOT * EMBED];
__device__ float g_K[(size_t)MTOT * EMBED];
__device__ float g_V[(size_t)MTOT * EMBED];

// ---------------------------------------------------------------------------
// NT GEMM tile accumulator: C[m,n] += sum_k A[m,k] * B[n,k]
// A: row-major [M, Kdim] (lda), B: row-major [N, Kdim] (ldb).
// Block computes BM x BN tile at (rowBase, colBase). All dims divide evenly.
// ---------------------------------------------------------------------------
__device__ __forceinline__ void gemm_nt_acc(
    const float* __restrict__ A, int lda,
    const float* __restrict__ B, int ldb,
    int Kdim, int rowBase, int colBase,
    float acc[TM][TN])
{
    __shared__ float As[BK][BM];
    __shared__ float Bs[BK][BN];
    const int tid   = threadIdx.x;
    const int tm    = tid >> 4;       // 0..15
    const int tn    = tid & 15;       // 0..15
    const int ldRow = tid >> 1;       // 0..127
    const int ldCol = (tid & 1) * 4;  // 0 or 4

    for (int k0 = 0; k0 < Kdim; k0 += BK) {
        float4 av = *reinterpret_cast<const float4*>(
            &A[(size_t)(rowBase + ldRow) * lda + k0 + ldCol]);
        float4 bv = *reinterpret_cast<const float4*>(
            &B[(size_t)(colBase + ldRow) * ldb + k0 + ldCol]);
        __syncthreads();
        As[ldCol + 0][ldRow] = av.x;
        As[ldCol + 1][ldRow] = av.y;
        As[ldCol + 2][ldRow] = av.z;
        As[ldCol + 3][ldRow] = av.w;
        Bs[ldCol + 0][ldRow] = bv.x;
        Bs[ldCol + 1][ldRow] = bv.y;
        Bs[ldCol + 2][ldRow] = bv.z;
        Bs[ldCol + 3][ldRow] = bv.w;
        __syncthreads();
#pragma unroll
        for (int kk = 0; kk < BK; kk++) {
            float4 a0 = *reinterpret_cast<const float4*>(&As[kk][tm * TM]);
            float4 a1 = *reinterpret_cast<const float4*>(&As[kk][tm * TM + 4]);
            float4 b0 = *reinterpret_cast<const float4*>(&Bs[kk][tn * TN]);
            float4 b1 = *reinterpret_cast<const float4*>(&Bs[kk][tn * TN + 4]);
            float ra[TM] = {a0.x, a0.y, a0.z, a0.w, a1.x, a1.y, a1.z, a1.w};
            float rb[TN] = {b0.x, b0.y, b0.z, b0.w, b1.x, b1.y, b1.z, b1.w};
#pragma unroll
            for (int i = 0; i < TM; i++)
#pragma unroll
                for (int j = 0; j < TN; j++)
                    acc[i][j] = fmaf(ra[i], rb[j], acc[i][j]);
        }
    }
}

// ---------------------------------------------------------------------------
// NN GEMM tile accumulator: C[m,n] += sum_k A[m,k] * B[k,n]
// A: row-major [M, Kdim] (lda), B: row-major [Kdim, N] (ldb).
// ---------------------------------------------------------------------------
__device__ __forceinline__ void gemm_nn_acc(
    const float* __restrict__ A, int lda,
    const float* __restrict__ B, int ldb,
    int Kdim, int rowBase, int colBase,
    float acc[TM][TN])
{
    __shared__ float As[BK][BM];
    __shared__ float Bs[BK][BN];
    const int tid   = threadIdx.x;
    const int tm    = tid >> 4;
    const int tn    = tid & 15;
    const int aRow  = tid >> 1;        // 0..127
    const int aCol  = (tid & 1) * 4;   // 0 or 4
    const int bRow  = tid >> 5;        // 0..7
    const int bCol  = (tid & 31) * 4;  // 0..124

    for (int k0 = 0; k0 < Kdim; k0 += BK) {
        float4 av = *reinterpret_cast<const float4*>(
            &A[(size_t)(rowBase + aRow) * lda + k0 + aCol]);
        float4 bv = *reinterpret_cast<const float4*>(
            &B[(size_t)(k0 + bRow) * ldb + colBase + bCol]);
        __syncthreads();
        As[aCol + 0][aRow] = av.x;
        As[aCol + 1][aRow] = av.y;
        As[aCol + 2][aRow] = av.z;
        As[aCol + 3][aRow] = av.w;
        *reinterpret_cast<float4*>(&Bs[bRow][bCol]) = bv;
        __syncthreads();
#pragma unroll
        for (int kk = 0; kk < BK; kk++) {
            float4 a0 = *reinterpret_cast<const float4*>(&As[kk][tm * TM]);
            float4 a1 = *reinterpret_cast<const float4*>(&As[kk][tm * TM + 4]);
            float4 b0 = *reinterpret_cast<const float4*>(&Bs[kk][tn * TN]);
            float4 b1 = *reinterpret_cast<const float4*>(&Bs[kk][tn * TN + 4]);
            float ra[TM] = {a0.x, a0.y, a0.z, a0.w, a1.x, a1.y, a1.z, a1.w};
            float rb[TN] = {b0.x, b0.y, b0.z, b0.w, b1.x, b1.y, b1.z, b1.w};
#pragma unroll
            for (int i = 0; i < TM; i++)
#pragma unroll
                for (int j = 0; j < TN; j++)
                    acc[i][j] = fmaf(ra[i], rb[j], acc[i][j]);
        }
    }
}

// ---------------------------------------------------------------------------
// Kernel 1: QKV projection. Q = x @ Wq^T + bq (torch Linear), etc.
// x: [MTOT, EMBED], W: [EMBED, EMBED] (out_dim major), NT GEMM.
// blockIdx.z selects Q/K/V.
// ---------------------------------------------------------------------------
__global__ __launch_bounds__(NTHREADS)
void qkv_kernel(const float* __restrict__ x,
                const float* __restrict__ Wq, const float* __restrict__ bq,
                const float* __restrict__ Wk, const float* __restrict__ bk,
                const float* __restrict__ Wv, const float* __restrict__ bv)
{
    const float* W; const float* bias; float* outp;
    if (blockIdx.z == 0)      { W = Wq; bias = bq; outp = g_Q; }
    else if (blockIdx.z == 1) { W = Wk; bias = bk; outp = g_K; }
    else                      { W = Wv; bias = bv; outp = g_V; }

    const int rowBase = blockIdx.y * BM;
    const int colBase = blockIdx.x * BN;
    float acc[TM][TN] = {};
    gemm_nt_acc(x, EMBED, W, EMBED, EMBED, rowBase, colBase, acc);

    const int tm = threadIdx.x >> 4, tn = threadIdx.x & 15;
#pragma unroll
    for (int i = 0; i < TM; i++) {
        const int r = rowBase + tm * TM + i;
#pragma unroll
        for (int j = 0; j < TN; j += 4) {
            const int c = colBase + tn * TN + j;
            float4 bvv = *reinterpret_cast<const float4*>(&bias[c]);
            float4 v;
            v.x = acc[i][j + 0] + bvv.x;
            v.y = acc[i][j + 1] + bvv.y;
            v.z = acc[i][j + 2] + bvv.z;
            v.w = acc[i][j + 3] + bvv.w;
            *reinterpret_cast<float4*>(&outp[(size_t)r * EMBED + c]) = v;
        }
    }
}

// ---------------------------------------------------------------------------
// Kernel 2: scores[b,q,k] = (Q[b,q,:] . K[b,k,:]) / 32 + (k>q ? -999 : 0)
// Written raw into the wts region of d_out (softmax happens in place next).
// ---------------------------------------------------------------------------
__global__ __launch_bounds__(NTHREADS)
void scores_kernel(float* __restrict__ wts)
{
    const int b = blockIdx.z;
    const float* Q  = g_Q + (size_t)b * SEQ * EMBED;
    const float* Kp = g_K + (size_t)b * SEQ * EMBED;
    float* S = wts + (size_t)b * SEQ * SEQ;

    const int rowBase = blockIdx.y * BM;
    const int colBase = blockIdx.x * BN;
    float acc[TM][TN] = {};
    gemm_nt_acc(Q, EMBED, Kp, EMBED, EMBED, rowBase, colBase, acc);

    const float scale = 0.03125f;  // 1/sqrt(1024)
    const int tm = threadIdx.x >> 4, tn = threadIdx.x & 15;
#pragma unroll
    for (int i = 0; i < TM; i++) {
        const int r = rowBase + tm * TM + i;
#pragma unroll
        for (int j = 0; j < TN; j += 4) {
            const int c = colBase + tn * TN + j;
            float4 v;
            v.x = acc[i][j + 0] * scale + ((c + 0) > r ? -999.0f : 0.0f);
            v.y = acc[i][j + 1] * scale + ((c + 1) > r ? -999.0f : 0.0f);
            v.z = acc[i][j + 2] * scale + ((c + 2) > r ? -999.0f : 0.0f);
            v.w = acc[i][j + 3] * scale + ((c + 3) > r ? -999.0f : 0.0f);
            *reinterpret_cast<float4*>(&S[(size_t)r * SEQ + c]) = v;
        }
    }
}

// ---------------------------------------------------------------------------
// Kernel 3: in-place row softmax over wts rows of length SEQ=2048.
// One block (256 threads) per row; 8 elements per thread.
// ---------------------------------------------------------------------------
__global__ __launch_bounds__(256)
void softmax_kernel(float* __restrict__ wts)
{
    float* p = wts + (size_t)blockIdx.x * SEQ;
    const int t = threadIdx.x;
    __shared__ float red[8];

    float v[8];
    float mx = -1e30f;
#pragma unroll
    for (int i = 0; i < 8; i++) {
        v[i] = p[t + i * 256];
        mx = fmaxf(mx, v[i]);
    }
#pragma unroll
    for (int o = 16; o > 0; o >>= 1) mx = fmaxf(mx, __shfl_xor_sync(0xffffffffu, mx, o));
    if ((t & 31) == 0) red[t >> 5] = mx;
    __syncthreads();
    float mxall = red[0];
#pragma unroll
    for (int i = 1; i < 8; i++) mxall = fmaxf(mxall, red[i]);
    __syncthreads();

    float s = 0.0f;
#pragma unroll
    for (int i = 0; i < 8; i++) {
        v[i] = __expf(v[i] - mxall);
        s += v[i];
    }
#pragma unroll
    for (int o = 16; o > 0; o >>= 1) s += __shfl_xor_sync(0xffffffffu, s, o);
    if ((t & 31) == 0) red[t >> 5] = s;
    __syncthreads();
    float total = 0.0f;
#pragma unroll
    for (int i = 0; i < 8; i++) total += red[i];
    const float inv = 1.0f / total;
#pragma unroll
    for (int i = 0; i < 8; i++) p[t + i * 256] = v[i] * inv;
}

// ---------------------------------------------------------------------------
// Kernel 4: out[b] = wts[b] @ V[b]   (NN GEMM, M=SEQ, N=EMBED, K=SEQ)
// ---------------------------------------------------------------------------
__global__ __launch_bounds__(NTHREADS)
void av_kernel(const float* __restrict__ wts, float* __restrict__ out)
{
    const int b = blockIdx.z;
    const float* A  = wts + (size_t)b * SEQ * SEQ;
    const float* Bv = g_V + (size_t)b * SEQ * EMBED;
    float* C = out + (size_t)b * SEQ * EMBED;

    const int rowBase = blockIdx.y * BM;
    const int colBase = blockIdx.x * BN;
    float acc[TM][TN] = {};
    gemm_nn_acc(A, SEQ, Bv, EMBED, SEQ, rowBase, colBase, acc);

    const int tm = threadIdx.x >> 4, tn = threadIdx.x & 15;
#pragma unroll
    for (int i = 0; i < TM; i++) {
        const int r = rowBase + tm * TM + i;
#pragma unroll
        for (int j = 0; j < TN; j += 4) {
            const int c = colBase + tn * TN + j;
            float4 v;
            v.x = acc[i][j + 0];
            v.y = acc[i][j + 1];
            v.z = acc[i][j + 2];
            v.w = acc[i][j + 3];
            *reinterpret_cast<float4*>(&C[(size_t)r * EMBED + c]) = v;
        }
    }
}

// ---------------------------------------------------------------------------
// Launch: inputs in metadata order x, Wq, bq, Wk, bk, Wv, bv.
// d_out = [ out : MTOT*EMBED floats ][ wts : BATCH*SEQ*SEQ floats ]
// ---------------------------------------------------------------------------
extern "C" void kernel_launch(void* const* d_in, const int* in_sizes, int n_in,
                              void* d_out, int out_size)
{
    const float* x  = (const float*)d_in[0];
    const float* Wq = (const float*)d_in[1];
    const float* bq = (const float*)d_in[2];
    const float* Wk = (const float*)d_in[3];
    const float* bk = (const float*)d_in[4];
    const float* Wv = (const float*)d_in[5];
    const float* bv = (const float*)d_in[6];

    float* out = (float*)d_out;
    float* wts = out + (size_t)MTOT * EMBED;

    dim3 blk(NTHREADS);
    qkv_kernel<<<dim3(EMBED / BN, MTOT / BM, 3), blk>>>(x, Wq, bq, Wk, bk, Wv, bv);
    scores_kernel<<<dim3(SEQ / BN, SEQ / BM, BATCH), blk>>>(wts);
    softmax_kernel<<<dim3(MTOT), dim3(256)>>>(wts);
    av_kernel<<<dim3(EMBED / BN, SEQ / BM, BATCH), blk>>>(wts, out);
}

// round 3
// speedup vs baseline: 1.8934x; 1.8934x over previous
#include <cuda_runtime.h>
#include <cuda_bf16.h>
#include <stdint.h>

#define EMBED 1024
#define BATCH 4
#define SEQ   2048
#define MTOT  (BATCH * SEQ)   // 8192

#define BM 128
#define BN 128
#define BK 16                 // fp32 k per stage
#define NTHREADS 256

#define PITCH  48             // bytes per SMEM row: 32B data (16 bf16) + 16B pad
#define TILEB  (128 * PITCH)  // 6144 B per bf16 tile
#define STAGEB (4 * TILEB)    // Ah, Al, Bh, Bl : 24576 B
#define SMEM_DYN (2 * STAGEB) // 49152 B == default dynamic smem limit (no attr needed)

// Scratch (device globals: no allocation anywhere)
__device__ float g_Q [(size_t)MTOT * EMBED];
__device__ float g_K [(size_t)MTOT * EMBED];
__device__ float g_Vt[(size_t)BATCH * EMBED * SEQ];   // V transposed: [b][e][s]

// ---------------------------------------------------------------------------
__device__ __forceinline__ uint32_t smem_u32(const void* p) {
    uint32_t a;
    asm("{ .reg .u64 t; cvta.to.shared.u64 t, %1; cvt.u32.u64 %0, t; }"
        : "=r"(a) : "l"(p));
    return a;
}

#define LDSM4(r0, r1, r2, r3, addr)                                          \
    asm volatile("ldmatrix.sync.aligned.m8n8.x4.shared.b16 {%0,%1,%2,%3}, [%4];" \
                 : "=r"(r0), "=r"(r1), "=r"(r2), "=r"(r3) : "r"(addr))

#define MMA16816(d, a0, a1, a2, a3, b0, b1)                                  \
    asm volatile("mma.sync.aligned.m16n8k16.row.col.f32.bf16.bf16.f32 "      \
                 "{%0,%1,%2,%3}, {%4,%5,%6,%7}, {%8,%9}, {%0,%1,%2,%3};"     \
                 : "+f"(d[0]), "+f"(d[1]), "+f"(d[2]), "+f"(d[3])            \
                 : "r"(a0), "r"(a1), "r"(a2), "r"(a3), "r"(b0), "r"(b1))

// fp32 -> (hi, lo) bf16 split; pack 4 floats into 2+2 uint32
__device__ __forceinline__ void split4(float4 v, uint32_t& h01, uint32_t& h23,
                                       uint32_t& l01, uint32_t& l23) {
    __nv_bfloat16 h0 = __float2bfloat16(v.x);
    __nv_bfloat16 h1 = __float2bfloat16(v.y);
    __nv_bfloat16 h2 = __float2bfloat16(v.z);
    __nv_bfloat16 h3 = __float2bfloat16(v.w);
    __nv_bfloat16 l0 = __float2bfloat16(v.x - __bfloat162float(h0));
    __nv_bfloat16 l1 = __float2bfloat16(v.y - __bfloat162float(h1));
    __nv_bfloat16 l2 = __float2bfloat16(v.z - __bfloat162float(h2));
    __nv_bfloat16 l3 = __float2bfloat16(v.w - __bfloat162float(h3));
    h01 = (uint32_t)__bfloat16_as_ushort(h0) | ((uint32_t)__bfloat16_as_ushort(h1) << 16);
    h23 = (uint32_t)__bfloat16_as_ushort(h2) | ((uint32_t)__bfloat16_as_ushort(h3) << 16);
    l01 = (uint32_t)__bfloat16_as_ushort(l0) | ((uint32_t)__bfloat16_as_ushort(l1) << 16);
    l23 = (uint32_t)__bfloat16_as_ushort(l2) | ((uint32_t)__bfloat16_as_ushort(l3) << 16);
}

// ---------------------------------------------------------------------------
// NT GEMM core: C(128x128) += A(128xK) @ B(128xK)^T, fp32-accurate via
// bf16 hi/lo split (Ah*Bh + Ah*Bl + Al*Bh). acc is the mma C fragment set:
// acc[mt][nt][4], warp tile 64x32 (warps 2x4), m16n8k16.
// ---------------------------------------------------------------------------
__device__ __forceinline__ void gemm_nt_core(
    const float* __restrict__ A, int lda,
    const float* __restrict__ B, int ldb,
    int Kdim, int rowBase, int colBase,
    char* sm, float acc[4][4][4])
{
    const int tid  = threadIdx.x;
    const int warp = tid >> 5, lane = tid & 31;
    const int mW = (warp >> 2) * 64;
    const int nW = (warp & 3) * 32;

    // global loader mapping: 128 rows x 16 floats, float4 per thread x2 rows
    const int lr = tid >> 2;          // 0..63
    const int lc = (tid & 3) * 4;     // 0,4,8,12

    // ldmatrix lane mapping (same pattern for A and B tiles)
    const int grp = lane >> 3;
    const int rIn = (grp & 1) * 8 + (lane & 7);
    const int cIn = (grp >> 1) * 16;  // byte offset within row

    const uint32_t smBase = smem_u32(sm);
    const int NC = Kdim / BK;

    float4 pa[2], pb[2];

    // prologue: load + store chunk 0
    {
        const int k0 = 0;
#pragma unroll
        for (int i = 0; i < 2; i++) {
            pa[i] = *(const float4*)&A[(size_t)(rowBase + lr + 64 * i) * lda + k0 + lc];
            pb[i] = *(const float4*)&B[(size_t)(colBase + lr + 64 * i) * ldb + k0 + lc];
        }
        char* Ah = sm;  char* Al = sm + TILEB;
        char* Bh = sm + 2 * TILEB; char* Bl = sm + 3 * TILEB;
#pragma unroll
        for (int i = 0; i < 2; i++) {
            const int row = lr + 64 * i;
            uint32_t h01, h23, l01, l23;
            split4(pa[i], h01, h23, l01, l23);
            *(uint32_t*)(Ah + row * PITCH + lc * 2)     = h01;
            *(uint32_t*)(Ah + row * PITCH + lc * 2 + 4) = h23;
            *(uint32_t*)(Al + row * PITCH + lc * 2)     = l01;
            *(uint32_t*)(Al + row * PITCH + lc * 2 + 4) = l23;
            split4(pb[i], h01, h23, l01, l23);
            *(uint32_t*)(Bh + row * PITCH + lc * 2)     = h01;
            *(uint32_t*)(Bh + row * PITCH + lc * 2 + 4) = h23;
            *(uint32_t*)(Bl + row * PITCH + lc * 2)     = l01;
            *(uint32_t*)(Bl + row * PITCH + lc * 2 + 4) = l23;
        }
    }
    __syncthreads();

    for (int c = 0; c < NC; c++) {
        // prefetch next chunk into registers (latency hides under MMAs)
        if (c + 1 < NC) {
            const int k0 = (c + 1) * BK;
#pragma unroll
            for (int i = 0; i < 2; i++) {
                pa[i] = *(const float4*)&A[(size_t)(rowBase + lr + 64 * i) * lda + k0 + lc];
                pb[i] = *(const float4*)&B[(size_t)(colBase + lr + 64 * i) * ldb + k0 + lc];
            }
        }

        // compute on stage c&1
        {
            const uint32_t sA  = smBase + (c & 1) * STAGEB;
            const uint32_t sAl = sA + TILEB;
            const uint32_t sB  = sA + 2 * TILEB;
            const uint32_t sBl = sA + 3 * TILEB;

            uint32_t ah[4][4], al[4][4], bh[2][4], bl[2][4];
#pragma unroll
            for (int mt = 0; mt < 4; mt++) {
                const uint32_t off = (uint32_t)((mW + mt * 16 + rIn) * PITCH + cIn);
                LDSM4(ah[mt][0], ah[mt][1], ah[mt][2], ah[mt][3], sA + off);
                LDSM4(al[mt][0], al[mt][1], al[mt][2], al[mt][3], sAl + off);
            }
#pragma unroll
            for (int p = 0; p < 2; p++) {
                const uint32_t off = (uint32_t)((nW + p * 16 + rIn) * PITCH + cIn);
                LDSM4(bh[p][0], bh[p][1], bh[p][2], bh[p][3], sB + off);
                LDSM4(bl[p][0], bl[p][1], bl[p][2], bl[p][3], sBl + off);
            }
#pragma unroll
            for (int mt = 0; mt < 4; mt++) {
#pragma unroll
                for (int nt = 0; nt < 4; nt++) {
                    const int p = nt >> 1, s = nt & 1;
                    const uint32_t bh0 = bh[p][s], bh1 = bh[p][s + 2];
                    const uint32_t bl0 = bl[p][s], bl1 = bl[p][s + 2];
                    MMA16816(acc[mt][nt], ah[mt][0], ah[mt][1], ah[mt][2], ah[mt][3], bh0, bh1);
                    MMA16816(acc[mt][nt], ah[mt][0], ah[mt][1], ah[mt][2], ah[mt][3], bl0, bl1);
                    MMA16816(acc[mt][nt], al[mt][0], al[mt][1], al[mt][2], al[mt][3], bh0, bh1);
                }
            }
        }

        // store prefetched chunk into the other stage
        if (c + 1 < NC) {
            char* base = sm + ((c + 1) & 1) * STAGEB;
            char* Ah = base;  char* Al = base + TILEB;
            char* Bh = base + 2 * TILEB; char* Bl = base + 3 * TILEB;
#pragma unroll
            for (int i = 0; i < 2; i++) {
                const int row = lr + 64 * i;
                uint32_t h01, h23, l01, l23;
                split4(pa[i], h01, h23, l01, l23);
                *(uint32_t*)(Ah + row * PITCH + lc * 2)     = h01;
                *(uint32_t*)(Ah + row * PITCH + lc * 2 + 4) = h23;
                *(uint32_t*)(Al + row * PITCH + lc * 2)     = l01;
                *(uint32_t*)(Al + row * PITCH + lc * 2 + 4) = l23;
                split4(pb[i], h01, h23, l01, l23);
                *(uint32_t*)(Bh + row * PITCH + lc * 2)     = h01;
                *(uint32_t*)(Bh + row * PITCH + lc * 2 + 4) = h23;
                *(uint32_t*)(Bl + row * PITCH + lc * 2)     = l01;
                *(uint32_t*)(Bl + row * PITCH + lc * 2 + 4) = l23;
            }
        }
        __syncthreads();
    }
}

// ---------------------------------------------------------------------------
// Kernel 1: QKV projection (torch Linear: x @ W^T + b). z selects Q/K/V.
// V goes TRANSPOSED into g_Vt[b][e][s].
// ---------------------------------------------------------------------------
__global__ __launch_bounds__(NTHREADS, 1)
void qkv_k(const float* __restrict__ x,
           const float* __restrict__ Wq, const float* __restrict__ bq,
           const float* __restrict__ Wk, const float* __restrict__ bk,
           const float* __restrict__ Wv, const float* __restrict__ bv)
{
    extern __shared__ char sm[];
    const int which = blockIdx.z;
    const float* W    = (which == 0) ? Wq : (which == 1) ? Wk : Wv;
    const float* bias = (which == 0) ? bq : (which == 1) ? bk : bv;

    const int rowBase = blockIdx.y * BM;
    const int colBase = blockIdx.x * BN;

    float acc[4][4][4] = {};
    gemm_nt_core(x, EMBED, W, EMBED, EMBED, rowBase, colBase, sm, acc);

    const int warp = threadIdx.x >> 5, lane = threadIdx.x & 31;
    const int mW = (warp >> 2) * 64, nW = (warp & 3) * 32;
    float* outQK = (which == 0) ? g_Q : g_K;

#pragma unroll
    for (int mt = 0; mt < 4; mt++) {
#pragma unroll
        for (int nt = 0; nt < 4; nt++) {
            const int r0 = rowBase + mW + mt * 16 + (lane >> 2);
            const int c0 = colBase + nW + nt * 8 + 2 * (lane & 3);
            const float b0 = bias[c0], b1 = bias[c0 + 1];
            float v00 = acc[mt][nt][0] + b0, v01 = acc[mt][nt][1] + b1;
            float v10 = acc[mt][nt][2] + b0, v11 = acc[mt][nt][3] + b1;
            if (which < 2) {
                *(float2*)&outQK[(size_t)r0 * EMBED + c0]       = make_float2(v00, v01);
                *(float2*)&outQK[(size_t)(r0 + 8) * EMBED + c0] = make_float2(v10, v11);
            } else {
                const int b  = r0 >> 11, s  = r0 & (SEQ - 1);
                const int s8 = (r0 + 8) & (SEQ - 1);   // same batch (rows within 128-tile)
                g_Vt[((size_t)b * EMBED + c0)     * SEQ + s]  = v00;
                g_Vt[((size_t)b * EMBED + c0 + 1) * SEQ + s]  = v01;
                g_Vt[((size_t)b * EMBED + c0)     * SEQ + s8] = v10;
                g_Vt[((size_t)b * EMBED + c0 + 1) * SEQ + s8] = v11;
            }
        }
    }
}

// ---------------------------------------------------------------------------
// Kernel 2: raw scores into wts region: (Q.K^T)/32 + causal(-999)
// ---------------------------------------------------------------------------
__global__ __launch_bounds__(NTHREADS, 1)
void scores_k(float* __restrict__ wts)
{
    extern __shared__ char sm[];
    const int b = blockIdx.z;
    const float* Q  = g_Q + (size_t)b * SEQ * EMBED;
    const float* Kp = g_K + (size_t)b * SEQ * EMBED;
    float* S = wts + (size_t)b * SEQ * SEQ;

    const int rowBase = blockIdx.y * BM;
    const int colBase = blockIdx.x * BN;

    float acc[4][4][4] = {};
    gemm_nt_core(Q, EMBED, Kp, EMBED, EMBED, rowBase, colBase, sm, acc);

    const int warp = threadIdx.x >> 5, lane = threadIdx.x & 31;
    const int mW = (warp >> 2) * 64, nW = (warp & 3) * 32;
    const float scale = 0.03125f;

#pragma unroll
    for (int mt = 0; mt < 4; mt++) {
#pragma unroll
        for (int nt = 0; nt < 4; nt++) {
            const int q0 = rowBase + mW + mt * 16 + (lane >> 2);
            const int c0 = colBase + nW + nt * 8 + 2 * (lane & 3);
            float2 v0, v1;
            v0.x = acc[mt][nt][0] * scale + ((c0 + 0) > q0 ? -999.0f : 0.0f);
            v0.y = acc[mt][nt][1] * scale + ((c0 + 1) > q0 ? -999.0f : 0.0f);
            v1.x = acc[mt][nt][2] * scale + ((c0 + 0) > (q0 + 8) ? -999.0f : 0.0f);
            v1.y = acc[mt][nt][3] * scale + ((c0 + 1) > (q0 + 8) ? -999.0f : 0.0f);
            *(float2*)&S[(size_t)q0 * SEQ + c0]       = v0;
            *(float2*)&S[(size_t)(q0 + 8) * SEQ + c0] = v1;
        }
    }
}

// ---------------------------------------------------------------------------
// Kernel 3: in-place row softmax (rows of 2048), one 256-thread block per row
// ---------------------------------------------------------------------------
__global__ __launch_bounds__(256)
void softmax_kernel(float* __restrict__ wts)
{
    float* p = wts + (size_t)blockIdx.x * SEQ;
    const int t = threadIdx.x;
    __shared__ float red[8];

    float v[8];
    float mx = -1e30f;
#pragma unroll
    for (int i = 0; i < 8; i++) { v[i] = p[t + i * 256]; mx = fmaxf(mx, v[i]); }
#pragma unroll
    for (int o = 16; o > 0; o >>= 1) mx = fmaxf(mx, __shfl_xor_sync(0xffffffffu, mx, o));
    if ((t & 31) == 0) red[t >> 5] = mx;
    __syncthreads();
    float mxall = red[0];
#pragma unroll
    for (int i = 1; i < 8; i++) mxall = fmaxf(mxall, red[i]);
    __syncthreads();

    float s = 0.0f;
#pragma unroll
    for (int i = 0; i < 8; i++) { v[i] = __expf(v[i] - mxall); s += v[i]; }
#pragma unroll
    for (int o = 16; o > 0; o >>= 1) s += __shfl_xor_sync(0xffffffffu, s, o);
    if ((t & 31) == 0) red[t >> 5] = s;
    __syncthreads();
    float total = 0.0f;
#pragma unroll
    for (int i = 0; i < 8; i++) total += red[i];
    const float inv = 1.0f / total;
#pragma unroll
    for (int i = 0; i < 8; i++) p[t + i * 256] = v[i] * inv;
}

// ---------------------------------------------------------------------------
// Kernel 4: out = wts @ V  via Vt (NT: B[n=e][k=s] = Vt[e][s])
// ---------------------------------------------------------------------------
__global__ __launch_bounds__(NTHREADS, 1)
void av_k(const float* __restrict__ wts, float* __restrict__ out)
{
    extern __shared__ char sm[];
    const int b = blockIdx.z;
    const float* A  = wts + (size_t)b * SEQ * SEQ;
    const float* Bv = g_Vt + (size_t)b * EMBED * SEQ;
    float* C = out + (size_t)b * SEQ * EMBED;

    const int rowBase = blockIdx.y * BM;
    const int colBase = blockIdx.x * BN;

    float acc[4][4][4] = {};
    gemm_nt_core(A, SEQ, Bv, SEQ, SEQ, rowBase, colBase, sm, acc);

    const int warp = threadIdx.x >> 5, lane = threadIdx.x & 31;
    const int mW = (warp >> 2) * 64, nW = (warp & 3) * 32;

#pragma unroll
    for (int mt = 0; mt < 4; mt++) {
#pragma unroll
        for (int nt = 0; nt < 4; nt++) {
            const int r0 = rowBase + mW + mt * 16 + (lane >> 2);
            const int c0 = colBase + nW + nt * 8 + 2 * (lane & 3);
            *(float2*)&C[(size_t)r0 * EMBED + c0] =
                make_float2(acc[mt][nt][0], acc[mt][nt][1]);
            *(float2*)&C[(size_t)(r0 + 8) * EMBED + c0] =
                make_float2(acc[mt][nt][2], acc[mt][nt][3]);
        }
    }
}

// ---------------------------------------------------------------------------
extern "C" void kernel_launch(void* const* d_in, const int* in_sizes, int n_in,
                              void* d_out, int out_size)
{
    const float* x  = (const float*)d_in[0];
    const float* Wq = (const float*)d_in[1];
    const float* bq = (const float*)d_in[2];
    const float* Wk = (const float*)d_in[3];
    const float* bk = (const float*)d_in[4];
    const float* Wv = (const float*)d_in[5];
    const float* bv = (const float*)d_in[6];

    float* out = (float*)d_out;
    float* wts = out + (size_t)MTOT * EMBED;

    qkv_k<<<dim3(EMBED / BN, MTOT / BM, 3), NTHREADS, SMEM_DYN>>>(x, Wq, bq, Wk, bk, Wv, bv);
    scores_k<<<dim3(SEQ / BN, SEQ / BM, BATCH), NTHREADS, SMEM_DYN>>>(wts);
    softmax_kernel<<<dim3(MTOT), dim3(256)>>>(wts);
    av_k<<<dim3(EMBED / BN, SEQ / BM, BATCH), NTHREADS, SMEM_DYN>>>(wts, out);
}

// round 4
// speedup vs baseline: 3.1539x; 1.6657x over previous
#include <cuda_runtime.h>
#include <cuda_bf16.h>
#include <stdint.h>

#define EMBED 1024
#define BATCH 4
#define SEQ   2048
#define MTOT  (BATCH * SEQ)   // 8192

#define BKH 32                 // bf16 k elements per stage
#define NTHREADS 256

#define PITCH  80              // bytes/SMEM row: 64B data (32 bf16) + 16B pad
#define TILEB  (128 * PITCH)   // 10240 B
#define STAGEB (4 * TILEB)     // 40960 B (Ah, Al, Bh, Bl)
#define SMEM_DYN (2 * STAGEB)  // 81920 B

// ---------------- scratch (device globals; bf16 split operands) ------------
__device__ __align__(128) __nv_bfloat16 g_xh[(size_t)MTOT * EMBED];
__device__ __align__(128) __nv_bfloat16 g_xl[(size_t)MTOT * EMBED];
__device__ __align__(128) __nv_bfloat16 g_Wh[(size_t)3 * EMBED * EMBED];
__device__ __align__(128) __nv_bfloat16 g_Wl[(size_t)3 * EMBED * EMBED];
__device__ __align__(128) __nv_bfloat16 g_Qh[(size_t)MTOT * EMBED];
__device__ __align__(128) __nv_bfloat16 g_Ql[(size_t)MTOT * EMBED];
__device__ __align__(128) __nv_bfloat16 g_Kh[(size_t)MTOT * EMBED];
__device__ __align__(128) __nv_bfloat16 g_Kl[(size_t)MTOT * EMBED];
__device__ __align__(128) __nv_bfloat16 g_Vth[(size_t)BATCH * EMBED * SEQ]; // [b][e][s]
__device__ __align__(128) __nv_bfloat16 g_Vtl[(size_t)BATCH * EMBED * SEQ];
__device__ __align__(128) __nv_bfloat16 g_wh[(size_t)BATCH * SEQ * SEQ];    // [b][q][k]
__device__ __align__(128) __nv_bfloat16 g_wl[(size_t)BATCH * SEQ * SEQ];

// ---------------------------------------------------------------------------
__device__ __forceinline__ uint32_t smem_u32(const void* p) {
    uint32_t a;
    asm("{ .reg .u64 t; cvta.to.shared.u64 t, %1; cvt.u32.u64 %0, t; }"
        : "=r"(a) : "l"(p));
    return a;
}

__device__ __forceinline__ void cp16(uint32_t saddr, const void* g) {
    asm volatile("cp.async.cg.shared.global [%0], [%1], 16;"
                 :: "r"(saddr), "l"(g));
}

#define LDSM4(r0, r1, r2, r3, addr)                                          \
    asm volatile("ldmatrix.sync.aligned.m8n8.x4.shared.b16 {%0,%1,%2,%3}, [%4];" \
                 : "=r"(r0), "=r"(r1), "=r"(r2), "=r"(r3) : "r"(addr))

#define MMA16816(d, a0, a1, a2, a3, b0, b1)                                  \
    asm volatile("mma.sync.aligned.m16n8k16.row.col.f32.bf16.bf16.f32 "      \
                 "{%0,%1,%2,%3}, {%4,%5,%6,%7}, {%8,%9}, {%0,%1,%2,%3};"     \
                 : "+f"(d[0]), "+f"(d[1]), "+f"(d[2]), "+f"(d[3])            \
                 : "r"(a0), "r"(a1), "r"(a2), "r"(a3), "r"(b0), "r"(b1))

__device__ __forceinline__ uint32_t packb(__nv_bfloat16 a, __nv_bfloat16 b) {
    return (uint32_t)__bfloat16_as_ushort(a) |
           ((uint32_t)__bfloat16_as_ushort(b) << 16);
}

// split v into hi/lo bf16
__device__ __forceinline__ void split1(float v, __nv_bfloat16& h, __nv_bfloat16& l) {
    h = __float2bfloat16(v);
    l = __float2bfloat16(v - __bfloat162float(h));
}

// write two consecutive elements (idx even) as packed bf16x2 into hi/lo arrays
__device__ __forceinline__ void split2_store(__nv_bfloat16* oh, __nv_bfloat16* ol,
                                             size_t idx, float v0, float v1) {
    __nv_bfloat16 h0, l0, h1, l1;
    split1(v0, h0, l0); split1(v1, h1, l1);
    *reinterpret_cast<uint32_t*>(oh + idx) = packb(h0, h1);
    *reinterpret_cast<uint32_t*>(ol + idx) = packb(l0, l1);
}

// ---------------------------------------------------------------------------
// cp.async one K-chunk (32 bf16) of the 4 tiles into a stage
// ---------------------------------------------------------------------------
__device__ __forceinline__ void issue_chunk(
    uint32_t smStage,
    const __nv_bfloat16* __restrict__ Ah, const __nv_bfloat16* __restrict__ Al,
    int lda, int rowBase,
    const __nv_bfloat16* __restrict__ Bh, const __nv_bfloat16* __restrict__ Bl,
    int ldb, int colBase, int k0)
{
    const int tid = threadIdx.x;
#pragma unroll
    for (int i = 0; i < 8; i++) {
        const int id   = tid + 256 * i;
        const int tile = id >> 9;          // 0..3
        const int row  = (id & 511) >> 2;  // 0..127
        const int cc   = id & 3;           // 16B chunk in row
        const __nv_bfloat16* g;
        if (tile == 0)      g = Ah + (size_t)(rowBase + row) * lda + k0 + cc * 8;
        else if (tile == 1) g = Al + (size_t)(rowBase + row) * lda + k0 + cc * 8;
        else if (tile == 2) g = Bh + (size_t)(colBase + row) * ldb + k0 + cc * 8;
        else                g = Bl + (size_t)(colBase + row) * ldb + k0 + cc * 8;
        cp16(smStage + tile * TILEB + row * PITCH + cc * 16, g);
    }
    asm volatile("cp.async.commit_group;" ::: "memory");
}

// ---------------------------------------------------------------------------
// compute one stage: 2 k-steps of m16n8k16, 3 split terms
// ---------------------------------------------------------------------------
__device__ __forceinline__ void compute_stage(uint32_t sst, int mW, int nW,
                                              int rIn, int cInB,
                                              float acc[4][4][4])
{
#pragma unroll
    for (int ks = 0; ks < 2; ks++) {
        const int cIn = cInB + ks * 32;
        uint32_t bh[2][4], bl[2][4];
#pragma unroll
        for (int p = 0; p < 2; p++) {
            const uint32_t off = (uint32_t)((nW + p * 16 + rIn) * PITCH + cIn);
            LDSM4(bh[p][0], bh[p][1], bh[p][2], bh[p][3], sst + 2 * TILEB + off);
            LDSM4(bl[p][0], bl[p][1], bl[p][2], bl[p][3], sst + 3 * TILEB + off);
        }
#pragma unroll
        for (int mt = 0; mt < 4; mt++) {
            const uint32_t off = (uint32_t)((mW + mt * 16 + rIn) * PITCH + cIn);
            uint32_t ah[4], al[4];
            LDSM4(ah[0], ah[1], ah[2], ah[3], sst + off);
            LDSM4(al[0], al[1], al[2], al[3], sst + TILEB + off);
#pragma unroll
            for (int nt = 0; nt < 4; nt++) {
                const int p = nt >> 1, s = nt & 1;
                MMA16816(acc[mt][nt], ah[0], ah[1], ah[2], ah[3], bh[p][s], bh[p][s + 2]);
                MMA16816(acc[mt][nt], ah[0], ah[1], ah[2], ah[3], bl[p][s], bl[p][s + 2]);
                MMA16816(acc[mt][nt], al[0], al[1], al[2], al[3], bh[p][s], bh[p][s + 2]);
            }
        }
    }
}

// ---------------------------------------------------------------------------
// NT GEMM core, double-buffered cp.async
// ---------------------------------------------------------------------------
__device__ __forceinline__ void gemm_core(
    const __nv_bfloat16* __restrict__ Ah, const __nv_bfloat16* __restrict__ Al,
    int lda, int rowBase,
    const __nv_bfloat16* __restrict__ Bh, const __nv_bfloat16* __restrict__ Bl,
    int ldb, int colBase,
    int Kdim, char* sm, float acc[4][4][4])
{
    const uint32_t smBase = smem_u32(sm);
    const int lane = threadIdx.x & 31;
    const int warp = threadIdx.x >> 5;
    const int mW = (warp >> 2) * 64, nW = (warp & 3) * 32;
    const int grp = lane >> 3;
    const int rIn = (grp & 1) * 8 + (lane & 7);
    const int cInB = (grp >> 1) * 16;

    const int NC = Kdim / BKH;
    issue_chunk(smBase, Ah, Al, lda, rowBase, Bh, Bl, ldb, colBase, 0);
    for (int c = 0; c < NC; c++) {
        if (c + 1 < NC) {
            issue_chunk(smBase + ((c + 1) & 1) * STAGEB, Ah, Al, lda, rowBase,
                        Bh, Bl, ldb, colBase, (c + 1) * BKH);
            asm volatile("cp.async.wait_group 1;" ::: "memory");
        } else {
            asm volatile("cp.async.wait_group 0;" ::: "memory");
        }
        __syncthreads();
        compute_stage(smBase + (c & 1) * STAGEB, mW, nW, rIn, cInB, acc);
        __syncthreads();
    }
}

// ---------------------------------------------------------------------------
// Kernel 0: fp32 -> bf16 hi/lo split (x and W pre-pass)
// ---------------------------------------------------------------------------
__global__ __launch_bounds__(256)
void split_k(const float* __restrict__ in, __nv_bfloat16* __restrict__ oh,
             __nv_bfloat16* __restrict__ ol, int n4)
{
    const int i = blockIdx.x * 256 + threadIdx.x;
    if (i >= n4) return;
    float4 v = reinterpret_cast<const float4*>(in)[i];
    __nv_bfloat16 h0, l0, h1, l1, h2, l2, h3, l3;
    split1(v.x, h0, l0); split1(v.y, h1, l1);
    split1(v.z, h2, l2); split1(v.w, h3, l3);
    uint2 hp = make_uint2(packb(h0, h1), packb(h2, h3));
    uint2 lp = make_uint2(packb(l0, l1), packb(l2, l3));
    reinterpret_cast<uint2*>(oh)[i] = hp;
    reinterpret_cast<uint2*>(ol)[i] = lp;
}

// ---------------------------------------------------------------------------
// Kernel 1: QKV projection. z selects Q/K/V. Emits split bf16 outputs.
// V goes transposed into g_Vth/g_Vtl via SMEM staging.
// ---------------------------------------------------------------------------
__global__ __launch_bounds__(NTHREADS, 2)
void qkv_k(const float* __restrict__ bq, const float* __restrict__ bk,
           const float* __restrict__ bv)
{
    extern __shared__ char sm[];
    const int which = blockIdx.z;
    const float* bias = (which == 0) ? bq : (which == 1) ? bk : bv;
    const __nv_bfloat16* Wh = g_Wh + (size_t)which * EMBED * EMBED;
    const __nv_bfloat16* Wl = g_Wl + (size_t)which * EMBED * EMBED;

    const int rowBase = blockIdx.y * 128;
    const int colBase = blockIdx.x * 128;

    float acc[4][4][4] = {};
    gemm_core(g_xh, g_xl, EMBED, rowBase, Wh, Wl, EMBED, colBase, EMBED, sm, acc);

    const int warp = threadIdx.x >> 5, lane = threadIdx.x & 31;
    const int mW = (warp >> 2) * 64, nW = (warp & 3) * 32;

    if (which < 2) {
        __nv_bfloat16* oh = (which == 0) ? g_Qh : g_Kh;
        __nv_bfloat16* ol = (which == 0) ? g_Ql : g_Kl;
#pragma unroll
        for (int mt = 0; mt < 4; mt++) {
#pragma unroll
            for (int nt = 0; nt < 4; nt++) {
                const int r0 = rowBase + mW + mt * 16 + (lane >> 2);
                const int c0 = colBase + nW + nt * 8 + 2 * (lane & 3);
                const float b0 = bias[c0], b1 = bias[c0 + 1];
                split2_store(oh, ol, (size_t)r0 * EMBED + c0,
                             acc[mt][nt][0] + b0, acc[mt][nt][1] + b1);
                split2_store(oh, ol, (size_t)(r0 + 8) * EMBED + c0,
                             acc[mt][nt][2] + b0, acc[mt][nt][3] + b1);
            }
        }
    } else {
        // stage transposed tile in SMEM: sh/sl are [e_rel(128)][s_rel pitch 136]
        __nv_bfloat16* sh = reinterpret_cast<__nv_bfloat16*>(sm);
        __nv_bfloat16* sl = sh + 128 * 136;
#pragma unroll
        for (int mt = 0; mt < 4; mt++) {
#pragma unroll
            for (int nt = 0; nt < 4; nt++) {
                const int rr = mW + mt * 16 + (lane >> 2);
                const int cc = nW + nt * 8 + 2 * (lane & 3);
                const float b0 = bias[colBase + cc], b1 = bias[colBase + cc + 1];
                float v00 = acc[mt][nt][0] + b0, v01 = acc[mt][nt][1] + b1;
                float v10 = acc[mt][nt][2] + b0, v11 = acc[mt][nt][3] + b1;
                __nv_bfloat16 h, l;
                split1(v00, h, l); sh[cc * 136 + rr] = h;       sl[cc * 136 + rr] = l;
                split1(v01, h, l); sh[(cc + 1) * 136 + rr] = h; sl[(cc + 1) * 136 + rr] = l;
                split1(v10, h, l); sh[cc * 136 + rr + 8] = h;   sl[cc * 136 + rr + 8] = l;
                split1(v11, h, l); sh[(cc + 1) * 136 + rr + 8] = h; sl[(cc + 1) * 136 + rr + 8] = l;
            }
        }
        __syncthreads();
        // coalesced copy-out: thread -> (e row, half)
        const int b = rowBase >> 11;
        const int sBase = rowBase & (SEQ - 1);
        const int erow = threadIdx.x >> 1, half = threadIdx.x & 1;
        const uint32_t* srcH = reinterpret_cast<const uint32_t*>(sh + erow * 136 + half * 64);
        const uint32_t* srcL = reinterpret_cast<const uint32_t*>(sl + erow * 136 + half * 64);
        const size_t dstE = ((size_t)(b * EMBED + colBase + erow) * SEQ + sBase + half * 64) >> 1;
        uint32_t* dH = reinterpret_cast<uint32_t*>(g_Vth) + dstE;
        uint32_t* dL = reinterpret_cast<uint32_t*>(g_Vtl) + dstE;
#pragma unroll
        for (int i = 0; i < 32; i++) { dH[i] = srcH[i]; dL[i] = srcL[i]; }
    }
}

// ---------------------------------------------------------------------------
// Kernel 2: raw scores (lower-triangle tiles only): (Q.K^T)/32 + mask(-999)
// ---------------------------------------------------------------------------
__global__ __launch_bounds__(NTHREADS, 2)
void scores_k(float* __restrict__ wts)
{
    if (blockIdx.x > blockIdx.y) return;   // fully masked tile: softmax writes 0
    extern __shared__ char sm[];
    const int b = blockIdx.z;
    const __nv_bfloat16* Qh = g_Qh + (size_t)b * SEQ * EMBED;
    const __nv_bfloat16* Ql = g_Ql + (size_t)b * SEQ * EMBED;
    const __nv_bfloat16* Kh = g_Kh + (size_t)b * SEQ * EMBED;
    const __nv_bfloat16* Kl = g_Kl + (size_t)b * SEQ * EMBED;
    float* S = wts + (size_t)b * SEQ * SEQ;

    const int rowBase = blockIdx.y * 128;
    const int colBase = blockIdx.x * 128;

    float acc[4][4][4] = {};
    gemm_core(Qh, Ql, EMBED, rowBase, Kh, Kl, EMBED, colBase, EMBED, sm, acc);

    const int warp = threadIdx.x >> 5, lane = threadIdx.x & 31;
    const int mW = (warp >> 2) * 64, nW = (warp & 3) * 32;
    const float scale = 0.03125f;

#pragma unroll
    for (int mt = 0; mt < 4; mt++) {
#pragma unroll
        for (int nt = 0; nt < 4; nt++) {
            const int q0 = rowBase + mW + mt * 16 + (lane >> 2);
            const int c0 = colBase + nW + nt * 8 + 2 * (lane & 3);
            float2 v0, v1;
            v0.x = acc[mt][nt][0] * scale + ((c0 + 0) > q0 ? -999.0f : 0.0f);
            v0.y = acc[mt][nt][1] * scale + ((c0 + 1) > q0 ? -999.0f : 0.0f);
            v1.x = acc[mt][nt][2] * scale + ((c0 + 0) > (q0 + 8) ? -999.0f : 0.0f);
            v1.y = acc[mt][nt][3] * scale + ((c0 + 1) > (q0 + 8) ? -999.0f : 0.0f);
            *(float2*)&S[(size_t)q0 * SEQ + c0]       = v0;
            *(float2*)&S[(size_t)(q0 + 8) * SEQ + c0] = v1;
        }
    }
}

// ---------------------------------------------------------------------------
// Kernel 3: softmax over valid prefix; emits fp32 wts + split bf16 w
// ---------------------------------------------------------------------------
__global__ __launch_bounds__(256)
void softmax_k(float* __restrict__ wts)
{
    const int row = blockIdx.x;            // 0..MTOT-1  (b*SEQ + q)
    const int q = row & (SEQ - 1);
    const int L = ((q >> 7) + 1) << 7;     // computed-score prefix length
    float* p = wts + (size_t)row * SEQ;
    __nv_bfloat16* wh = g_wh + (size_t)row * SEQ;
    __nv_bfloat16* wl = g_wl + (size_t)row * SEQ;
    const int t = threadIdx.x;
    __shared__ float red[8];

    float mx = -1e30f;
    for (int k = t; k < L; k += 256) mx = fmaxf(mx, p[k]);
#pragma unroll
    for (int o = 16; o > 0; o >>= 1) mx = fmaxf(mx, __shfl_xor_sync(0xffffffffu, mx, o));
    if ((t & 31) == 0) red[t >> 5] = mx;
    __syncthreads();
    float mxall = red[0];
#pragma unroll
    for (int i = 1; i < 8; i++) mxall = fmaxf(mxall, red[i]);
    __syncthreads();

    float v[8];
    float s = 0.0f;
    {
        int i = 0;
        for (int k = t; k < L; k += 256, i++) { v[i] = __expf(p[k] - mxall); s += v[i]; }
    }
#pragma unroll
    for (int o = 16; o > 0; o >>= 1) s += __shfl_xor_sync(0xffffffffu, s, o);
    if ((t & 31) == 0) red[t >> 5] = s;
    __syncthreads();
    float total = 0.0f;
#pragma unroll
    for (int i = 0; i < 8; i++) total += red[i];
    const float inv = 1.0f / total;

    {
        int i = 0;
        for (int k = t; k < L; k += 256, i++) {
            const float w = v[i] * inv;
            p[k] = w;
            __nv_bfloat16 h, l;
            split1(w, h, l);
            wh[k] = h; wl[k] = l;
        }
    }
    const __nv_bfloat16 z = __float2bfloat16(0.0f);
    for (int k = L + t; k < SEQ; k += 256) { p[k] = 0.0f; wh[k] = z; wl[k] = z; }
}

// ---------------------------------------------------------------------------
// Kernel 4: out = w @ V via split NT GEMM against Vt; K truncated causally
// ---------------------------------------------------------------------------
__global__ __launch_bounds__(NTHREADS, 2)
void av_k(float* __restrict__ out)
{
    extern __shared__ char sm[];
    const int b = blockIdx.z;
    const __nv_bfloat16* Ah = g_wh + (size_t)b * SEQ * SEQ;
    const __nv_bfloat16* Al = g_wl + (size_t)b * SEQ * SEQ;
    const __nv_bfloat16* Bh = g_Vth + (size_t)b * EMBED * SEQ;
    const __nv_bfloat16* Bl = g_Vtl + (size_t)b * EMBED * SEQ;
    float* C = out + (size_t)b * SEQ * EMBED;

    const int rowBase = blockIdx.y * 128;
    const int colBase = blockIdx.x * 128;
    const int Keff = rowBase + 128;        // causal truncation

    float acc[4][4][4] = {};
    gemm_core(Ah, Al, SEQ, rowBase, Bh, Bl, SEQ, colBase, Keff, sm, acc);

    const int warp = threadIdx.x >> 5, lane = threadIdx.x & 31;
    const int mW = (warp >> 2) * 64, nW = (warp & 3) * 32;

#pragma unroll
    for (int mt = 0; mt < 4; mt++) {
#pragma unroll
        for (int nt = 0; nt < 4; nt++) {
            const int r0 = rowBase + mW + mt * 16 + (lane >> 2);
            const int c0 = colBase + nW + nt * 8 + 2 * (lane & 3);
            *(float2*)&C[(size_t)r0 * EMBED + c0] =
                make_float2(acc[mt][nt][0], acc[mt][nt][1]);
            *(float2*)&C[(size_t)(r0 + 8) * EMBED + c0] =
                make_float2(acc[mt][nt][2], acc[mt][nt][3]);
        }
    }
}

// ---------------------------------------------------------------------------
extern "C" void kernel_launch(void* const* d_in, const int* in_sizes, int n_in,
                              void* d_out, int out_size)
{
    const float* x  = (const float*)d_in[0];
    const float* Wq = (const float*)d_in[1];
    const float* bq = (const float*)d_in[2];
    const float* Wk = (const float*)d_in[3];
    const float* bk = (const float*)d_in[4];
    const float* Wv = (const float*)d_in[5];
    const float* bv = (const float*)d_in[6];

    float* out = (float*)d_out;
    float* wts = out + (size_t)MTOT * EMBED;

    cudaFuncSetAttribute(qkv_k,    cudaFuncAttributeMaxDynamicSharedMemorySize, SMEM_DYN);
    cudaFuncSetAttribute(scores_k, cudaFuncAttributeMaxDynamicSharedMemorySize, SMEM_DYN);
    cudaFuncSetAttribute(av_k,     cudaFuncAttributeMaxDynamicSharedMemorySize, SMEM_DYN);

    // resolve device-symbol addresses (host side; cheap, no allocation)
    __nv_bfloat16 *xh, *xl, *Wh, *Wl;
    cudaGetSymbolAddress((void**)&xh, g_xh);
    cudaGetSymbolAddress((void**)&xl, g_xl);
    cudaGetSymbolAddress((void**)&Wh, g_Wh);
    cudaGetSymbolAddress((void**)&Wl, g_Wl);

    const int nx4 = MTOT * EMBED / 4;
    const int nw4 = EMBED * EMBED / 4;
    split_k<<<(nx4 + 255) / 256, 256>>>(x, xh, xl, nx4);
    split_k<<<(nw4 + 255) / 256, 256>>>(Wq, Wh,              Wl,              nw4);
    split_k<<<(nw4 + 255) / 256, 256>>>(Wk, Wh + nw4 * 4,    Wl + nw4 * 4,    nw4);
    split_k<<<(nw4 + 255) / 256, 256>>>(Wv, Wh + 2 * nw4 * 4, Wl + 2 * nw4 * 4, nw4);

    qkv_k<<<dim3(EMBED / 128, MTOT / 128, 3), NTHREADS, SMEM_DYN>>>(bq, bk, bv);
    scores_k<<<dim3(SEQ / 128, SEQ / 128, BATCH), NTHREADS, SMEM_DYN>>>(wts);
    softmax_k<<<dim3(MTOT), dim3(256)>>>(wts);
    av_k<<<dim3(EMBED / 128, SEQ / 128, BATCH), NTHREADS, SMEM_DYN>>>(out);
}

// round 5
// speedup vs baseline: 3.3451x; 1.0606x over previous
#include <cuda_runtime.h>
#include <cuda_bf16.h>
#include <stdint.h>

#define EMBED 1024
#define BATCH 4
#define SEQ   2048
#define MTOT  (BATCH * SEQ)   // 8192

#define BKH 32                 // bf16 k elements per stage
#define NTHREADS 256

#define ROWB   64              // bytes per SMEM row (no pad; XOR swizzle)
#define TILEB  (128 * ROWB)    // 8192 B
#define STAGEB (4 * TILEB)     // 32768 B (Ah, Al, Bh, Bl)
#define NSTAGE 3
#define SMEM_DYN (NSTAGE * STAGEB)  // 98304 B

// swizzle: rotate 16B chunks within the 64B row, 8-row period w/ the 64B<<1 wrap
#define SWZB(row, c) ((c) ^ ((((row) >> 1) & 3) << 4))

// ---------------- scratch (device globals; bf16 split operands) ------------
__device__ __align__(128) __nv_bfloat16 g_xh[(size_t)MTOT * EMBED];
__device__ __align__(128) __nv_bfloat16 g_xl[(size_t)MTOT * EMBED];
__device__ __align__(128) __nv_bfloat16 g_Wh[(size_t)3 * EMBED * EMBED];
__device__ __align__(128) __nv_bfloat16 g_Wl[(size_t)3 * EMBED * EMBED];
__device__ __align__(128) __nv_bfloat16 g_Qh[(size_t)MTOT * EMBED];
__device__ __align__(128) __nv_bfloat16 g_Ql[(size_t)MTOT * EMBED];
__device__ __align__(128) __nv_bfloat16 g_Kh[(size_t)MTOT * EMBED];
__device__ __align__(128) __nv_bfloat16 g_Kl[(size_t)MTOT * EMBED];
__device__ __align__(128) __nv_bfloat16 g_Vth[(size_t)BATCH * EMBED * SEQ]; // [b][e][s]
__device__ __align__(128) __nv_bfloat16 g_Vtl[(size_t)BATCH * EMBED * SEQ];
__device__ __align__(128) __nv_bfloat16 g_wh[(size_t)BATCH * SEQ * SEQ];    // [b][q][k]
__device__ __align__(128) __nv_bfloat16 g_wl[(size_t)BATCH * SEQ * SEQ];

// ---------------------------------------------------------------------------
__device__ __forceinline__ uint32_t smem_u32(const void* p) {
    uint32_t a;
    asm("{ .reg .u64 t; cvta.to.shared.u64 t, %1; cvt.u32.u64 %0, t; }"
        : "=r"(a) : "l"(p));
    return a;
}

__device__ __forceinline__ void cp16(uint32_t saddr, const void* g) {
    asm volatile("cp.async.cg.shared.global [%0], [%1], 16;"
                 :: "r"(saddr), "l"(g));
}

#define LDSM4(r0, r1, r2, r3, addr)                                          \
    asm volatile("ldmatrix.sync.aligned.m8n8.x4.shared.b16 {%0,%1,%2,%3}, [%4];" \
                 : "=r"(r0), "=r"(r1), "=r"(r2), "=r"(r3) : "r"(addr))

#define MMA16816(d, a0, a1, a2, a3, b0, b1)                                  \
    asm volatile("mma.sync.aligned.m16n8k16.row.col.f32.bf16.bf16.f32 "      \
                 "{%0,%1,%2,%3}, {%4,%5,%6,%7}, {%8,%9}, {%0,%1,%2,%3};"     \
                 : "+f"(d[0]), "+f"(d[1]), "+f"(d[2]), "+f"(d[3])            \
                 : "r"(a0), "r"(a1), "r"(a2), "r"(a3), "r"(b0), "r"(b1))

__device__ __forceinline__ uint32_t packb(__nv_bfloat16 a, __nv_bfloat16 b) {
    return (uint32_t)__bfloat16_as_ushort(a) |
           ((uint32_t)__bfloat16_as_ushort(b) << 16);
}

__device__ __forceinline__ void split1(float v, __nv_bfloat16& h, __nv_bfloat16& l) {
    h = __float2bfloat16(v);
    l = __float2bfloat16(v - __bfloat162float(h));
}

__device__ __forceinline__ void split2_store(__nv_bfloat16* oh, __nv_bfloat16* ol,
                                             size_t idx, float v0, float v1) {
    __nv_bfloat16 h0, l0, h1, l1;
    split1(v0, h0, l0); split1(v1, h1, l1);
    *reinterpret_cast<uint32_t*>(oh + idx) = packb(h0, h1);
    *reinterpret_cast<uint32_t*>(ol + idx) = packb(l0, l1);
}

// ---------------------------------------------------------------------------
// cp.async one K-chunk (32 bf16) of the 4 tiles into a stage, commit group
// ---------------------------------------------------------------------------
__device__ __forceinline__ void issue_chunk(
    uint32_t smStage,
    const __nv_bfloat16* __restrict__ Ah, const __nv_bfloat16* __restrict__ Al,
    int lda, int rowBase,
    const __nv_bfloat16* __restrict__ Bh, const __nv_bfloat16* __restrict__ Bl,
    int ldb, int colBase, int k0)
{
    const int tid = threadIdx.x;
#pragma unroll
    for (int i = 0; i < 8; i++) {
        const int id   = tid + 256 * i;
        const int tile = id >> 9;          // 0..3
        const int row  = (id & 511) >> 2;  // 0..127
        const int cc   = id & 3;           // 16B chunk in row
        const __nv_bfloat16* g;
        if (tile == 0)      g = Ah + (size_t)(rowBase + row) * lda + k0 + cc * 8;
        else if (tile == 1) g = Al + (size_t)(rowBase + row) * lda + k0 + cc * 8;
        else if (tile == 2) g = Bh + (size_t)(colBase + row) * ldb + k0 + cc * 8;
        else                g = Bl + (size_t)(colBase + row) * ldb + k0 + cc * 8;
        cp16(smStage + tile * TILEB + row * ROWB + SWZB(row, cc * 16), g);
    }
    asm volatile("cp.async.commit_group;" ::: "memory");
}

// ---------------------------------------------------------------------------
// compute one stage: 2 k-steps of m16n8k16, 3 split terms
// ---------------------------------------------------------------------------
__device__ __forceinline__ void compute_stage(uint32_t sst, int mW, int nW,
                                              int rIn, int cInB,
                                              float acc[4][4][4])
{
#pragma unroll
    for (int ks = 0; ks < 2; ks++) {
        const int cIn = cInB + ks * 32;
        uint32_t bh[2][4], bl[2][4];
#pragma unroll
        for (int p = 0; p < 2; p++) {
            const int row = nW + p * 16 + rIn;
            const uint32_t off = (uint32_t)(row * ROWB + SWZB(row, cIn));
            LDSM4(bh[p][0], bh[p][1], bh[p][2], bh[p][3], sst + 2 * TILEB + off);
            LDSM4(bl[p][0], bl[p][1], bl[p][2], bl[p][3], sst + 3 * TILEB + off);
        }
#pragma unroll
        for (int mt = 0; mt < 4; mt++) {
            const int row = mW + mt * 16 + rIn;
            const uint32_t off = (uint32_t)(row * ROWB + SWZB(row, cIn));
            uint32_t ah[4], al[4];
            LDSM4(ah[0], ah[1], ah[2], ah[3], sst + off);
            LDSM4(al[0], al[1], al[2], al[3], sst + TILEB + off);
#pragma unroll
            for (int nt = 0; nt < 4; nt++) {
                const int p = nt >> 1, s = nt & 1;
                MMA16816(acc[mt][nt], ah[0], ah[1], ah[2], ah[3], bh[p][s], bh[p][s + 2]);
                MMA16816(acc[mt][nt], ah[0], ah[1], ah[2], ah[3], bl[p][s], bl[p][s + 2]);
                MMA16816(acc[mt][nt], al[0], al[1], al[2], al[3], bh[p][s], bh[p][s + 2]);
            }
        }
    }
}

// ---------------------------------------------------------------------------
// NT GEMM core, 3-stage cp.async ring
// ---------------------------------------------------------------------------
__device__ __forceinline__ void gemm_core(
    const __nv_bfloat16* __restrict__ Ah, const __nv_bfloat16* __restrict__ Al,
    int lda, int rowBase,
    const __nv_bfloat16* __restrict__ Bh, const __nv_bfloat16* __restrict__ Bl,
    int ldb, int colBase,
    int Kdim, char* sm, float acc[4][4][4])
{
    const uint32_t smBase = smem_u32(sm);
    const int lane = threadIdx.x & 31;
    const int warp = threadIdx.x >> 5;
    const int mW = (warp >> 2) * 64, nW = (warp & 3) * 32;
    const int grp = lane >> 3;
    const int rIn = (grp & 1) * 8 + (lane & 7);
    const int cInB = (grp >> 1) * 16;

    const int NC = Kdim / BKH;   // >= 4 for all call sites
    issue_chunk(smBase,          Ah, Al, lda, rowBase, Bh, Bl, ldb, colBase, 0);
    issue_chunk(smBase + STAGEB, Ah, Al, lda, rowBase, Bh, Bl, ldb, colBase, BKH);

    int stage = 0;
    for (int c = 0; c < NC; c++) {
        if (c + 2 < NC) {
            int s2 = stage + 2; if (s2 >= NSTAGE) s2 -= NSTAGE;
            issue_chunk(smBase + s2 * STAGEB, Ah, Al, lda, rowBase,
                        Bh, Bl, ldb, colBase, (c + 2) * BKH);
        } else {
            asm volatile("cp.async.commit_group;" ::: "memory");  // empty group
        }
        asm volatile("cp.async.wait_group 2;" ::: "memory");
        __syncthreads();
        compute_stage(smBase + stage * STAGEB, mW, nW, rIn, cInB, acc);
        __syncthreads();
        if (++stage == NSTAGE) stage = 0;
    }
}

// ---------------------------------------------------------------------------
// Kernel 0: fp32 -> bf16 hi/lo split (x and W pre-pass)
// ---------------------------------------------------------------------------
__global__ __launch_bounds__(256)
void split_k(const float* __restrict__ in, __nv_bfloat16* __restrict__ oh,
             __nv_bfloat16* __restrict__ ol, int n4)
{
    const int i = blockIdx.x * 256 + threadIdx.x;
    if (i >= n4) return;
    float4 v = reinterpret_cast<const float4*>(in)[i];
    __nv_bfloat16 h0, l0, h1, l1, h2, l2, h3, l3;
    split1(v.x, h0, l0); split1(v.y, h1, l1);
    split1(v.z, h2, l2); split1(v.w, h3, l3);
    reinterpret_cast<uint2*>(oh)[i] = make_uint2(packb(h0, h1), packb(h2, h3));
    reinterpret_cast<uint2*>(ol)[i] = make_uint2(packb(l0, l1), packb(l2, l3));
}

// ---------------------------------------------------------------------------
// Kernel 1: QKV projection. z selects Q/K/V. Emits split bf16 outputs.
// V goes transposed into g_Vth/g_Vtl via SMEM staging.
// ---------------------------------------------------------------------------
__global__ __launch_bounds__(NTHREADS, 2)
void qkv_k(const float* __restrict__ bq, const float* __restrict__ bk,
           const float* __restrict__ bv)
{
    extern __shared__ char sm[];
    const int which = blockIdx.z;
    const float* bias = (which == 0) ? bq : (which == 1) ? bk : bv;
    const __nv_bfloat16* Wh = g_Wh + (size_t)which * EMBED * EMBED;
    const __nv_bfloat16* Wl = g_Wl + (size_t)which * EMBED * EMBED;

    const int rowBase = blockIdx.y * 128;
    const int colBase = blockIdx.x * 128;

    float acc[4][4][4] = {};
    gemm_core(g_xh, g_xl, EMBED, rowBase, Wh, Wl, EMBED, colBase, EMBED, sm, acc);

    const int warp = threadIdx.x >> 5, lane = threadIdx.x & 31;
    const int mW = (warp >> 2) * 64, nW = (warp & 3) * 32;

    if (which < 2) {
        __nv_bfloat16* oh = (which == 0) ? g_Qh : g_Kh;
        __nv_bfloat16* ol = (which == 0) ? g_Ql : g_Kl;
#pragma unroll
        for (int mt = 0; mt < 4; mt++) {
#pragma unroll
            for (int nt = 0; nt < 4; nt++) {
                const int r0 = rowBase + mW + mt * 16 + (lane >> 2);
                const int c0 = colBase + nW + nt * 8 + 2 * (lane & 3);
                const float b0 = bias[c0], b1 = bias[c0 + 1];
                split2_store(oh, ol, (size_t)r0 * EMBED + c0,
                             acc[mt][nt][0] + b0, acc[mt][nt][1] + b1);
                split2_store(oh, ol, (size_t)(r0 + 8) * EMBED + c0,
                             acc[mt][nt][2] + b0, acc[mt][nt][3] + b1);
            }
        }
    } else {
        // stage transposed tile in SMEM: [e_rel(128)][s_rel pitch 136]
        __nv_bfloat16* sh = reinterpret_cast<__nv_bfloat16*>(sm);
        __nv_bfloat16* sl = sh + 128 * 136;
#pragma unroll
        for (int mt = 0; mt < 4; mt++) {
#pragma unroll
            for (int nt = 0; nt < 4; nt++) {
                const int rr = mW + mt * 16 + (lane >> 2);
                const int cc = nW + nt * 8 + 2 * (lane & 3);
                const float b0 = bias[colBase + cc], b1 = bias[colBase + cc + 1];
                float v00 = acc[mt][nt][0] + b0, v01 = acc[mt][nt][1] + b1;
                float v10 = acc[mt][nt][2] + b0, v11 = acc[mt][nt][3] + b1;
                __nv_bfloat16 h, l;
                split1(v00, h, l); sh[cc * 136 + rr] = h;       sl[cc * 136 + rr] = l;
                split1(v01, h, l); sh[(cc + 1) * 136 + rr] = h; sl[(cc + 1) * 136 + rr] = l;
                split1(v10, h, l); sh[cc * 136 + rr + 8] = h;   sl[cc * 136 + rr + 8] = l;
                split1(v11, h, l); sh[(cc + 1) * 136 + rr + 8] = h; sl[(cc + 1) * 136 + rr + 8] = l;
            }
        }
        __syncthreads();
        const int b = rowBase >> 11;
        const int sBase = rowBase & (SEQ - 1);
        const int erow = threadIdx.x >> 1, half = threadIdx.x & 1;
        const uint32_t* srcH = reinterpret_cast<const uint32_t*>(sh + erow * 136 + half * 64);
        const uint32_t* srcL = reinterpret_cast<const uint32_t*>(sl + erow * 136 + half * 64);
        const size_t dstE = ((size_t)(b * EMBED + colBase + erow) * SEQ + sBase + half * 64) >> 1;
        uint32_t* dH = reinterpret_cast<uint32_t*>(g_Vth) + dstE;
        uint32_t* dL = reinterpret_cast<uint32_t*>(g_Vtl) + dstE;
#pragma unroll
        for (int i = 0; i < 32; i++) { dH[i] = srcH[i]; dL[i] = srcL[i]; }
    }
}

// ---------------------------------------------------------------------------
// Kernel 2: raw scores (lower-triangle tiles only): (Q.K^T)/32 + mask(-999)
// ---------------------------------------------------------------------------
__global__ __launch_bounds__(NTHREADS, 2)
void scores_k(float* __restrict__ wts)
{
    if (blockIdx.x > blockIdx.y) return;   // fully masked tile: softmax writes 0
    extern __shared__ char sm[];
    const int b = blockIdx.z;
    const __nv_bfloat16* Qh = g_Qh + (size_t)b * SEQ * EMBED;
    const __nv_bfloat16* Ql = g_Ql + (size_t)b * SEQ * EMBED;
    const __nv_bfloat16* Kh = g_Kh + (size_t)b * SEQ * EMBED;
    const __nv_bfloat16* Kl = g_Kl + (size_t)b * SEQ * EMBED;
    float* S = wts + (size_t)b * SEQ * SEQ;

    const int rowBase = blockIdx.y * 128;
    const int colBase = blockIdx.x * 128;

    float acc[4][4][4] = {};
    gemm_core(Qh, Ql, EMBED, rowBase, Kh, Kl, EMBED, colBase, EMBED, sm, acc);

    const int warp = threadIdx.x >> 5, lane = threadIdx.x & 31;
    const int mW = (warp >> 2) * 64, nW = (warp & 3) * 32;
    const float scale = 0.03125f;

#pragma unroll
    for (int mt = 0; mt < 4; mt++) {
#pragma unroll
        for (int nt = 0; nt < 4; nt++) {
            const int q0 = rowBase + mW + mt * 16 + (lane >> 2);
            const int c0 = colBase + nW + nt * 8 + 2 * (lane & 3);
            float2 v0, v1;
            v0.x = acc[mt][nt][0] * scale + ((c0 + 0) > q0 ? -999.0f : 0.0f);
            v0.y = acc[mt][nt][1] * scale + ((c0 + 1) > q0 ? -999.0f : 0.0f);
            v1.x = acc[mt][nt][2] * scale + ((c0 + 0) > (q0 + 8) ? -999.0f : 0.0f);
            v1.y = acc[mt][nt][3] * scale + ((c0 + 1) > (q0 + 8) ? -999.0f : 0.0f);
            *(float2*)&S[(size_t)q0 * SEQ + c0]       = v0;
            *(float2*)&S[(size_t)(q0 + 8) * SEQ + c0] = v1;
        }
    }
}

// ---------------------------------------------------------------------------
// Kernel 3: softmax over valid prefix; emits fp32 wts + split bf16 w
// ---------------------------------------------------------------------------
__global__ __launch_bounds__(256)
void softmax_k(float* __restrict__ wts)
{
    const int row = blockIdx.x;            // b*SEQ + q
    const int q = row & (SEQ - 1);
    const int L = ((q >> 7) + 1) << 7;     // computed-score prefix length
    float* p = wts + (size_t)row * SEQ;
    __nv_bfloat16* wh = g_wh + (size_t)row * SEQ;
    __nv_bfloat16* wl = g_wl + (size_t)row * SEQ;
    const int t = threadIdx.x;
    __shared__ float red[8];

    float mx = -1e30f;
    for (int k = t; k < L; k += 256) mx = fmaxf(mx, p[k]);
#pragma unroll
    for (int o = 16; o > 0; o >>= 1) mx = fmaxf(mx, __shfl_xor_sync(0xffffffffu, mx, o));
    if ((t & 31) == 0) red[t >> 5] = mx;
    __syncthreads();
    float mxall = red[0];
#pragma unroll
    for (int i = 1; i < 8; i++) mxall = fmaxf(mxall, red[i]);
    __syncthreads();

    float v[8];
    float s = 0.0f;
    {
        int i = 0;
        for (int k = t; k < L; k += 256, i++) { v[i] = __expf(p[k] - mxall); s += v[i]; }
    }
#pragma unroll
    for (int o = 16; o > 0; o >>= 1) s += __shfl_xor_sync(0xffffffffu, s, o);
    if ((t & 31) == 0) red[t >> 5] = s;
    __syncthreads();
    float total = 0.0f;
#pragma unroll
    for (int i = 0; i < 8; i++) total += red[i];
    const float inv = 1.0f / total;

    {
        int i = 0;
        for (int k = t; k < L; k += 256, i++) {
            const float w = v[i] * inv;
            p[k] = w;
            __nv_bfloat16 h, l;
            split1(w, h, l);
            wh[k] = h; wl[k] = l;
        }
    }
    const __nv_bfloat16 z = __float2bfloat16(0.0f);
    for (int k = L + t; k < SEQ; k += 256) { p[k] = 0.0f; wh[k] = z; wl[k] = z; }
}

// ---------------------------------------------------------------------------
// Kernel 4: out = w @ V via split NT GEMM against Vt; K truncated causally
// ---------------------------------------------------------------------------
__global__ __launch_bounds__(NTHREADS, 2)
void av_k(float* __restrict__ out)
{
    extern __shared__ char sm[];
    const int b = blockIdx.z;
    const __nv_bfloat16* Ah = g_wh + (size_t)b * SEQ * SEQ;
    const __nv_bfloat16* Al = g_wl + (size_t)b * SEQ * SEQ;
    const __nv_bfloat16* Bh = g_Vth + (size_t)b * EMBED * SEQ;
    const __nv_bfloat16* Bl = g_Vtl + (size_t)b * EMBED * SEQ;
    float* C = out + (size_t)b * SEQ * EMBED;

    const int rowBase = blockIdx.y * 128;
    const int colBase = blockIdx.x * 128;
    const int Keff = rowBase + 128;        // causal truncation

    float acc[4][4][4] = {};
    gemm_core(Ah, Al, SEQ, rowBase, Bh, Bl, SEQ, colBase, Keff, sm, acc);

    const int warp = threadIdx.x >> 5, lane = threadIdx.x & 31;
    const int mW = (warp >> 2) * 64, nW = (warp & 3) * 32;

#pragma unroll
    for (int mt = 0; mt < 4; mt++) {
#pragma unroll
        for (int nt = 0; nt < 4; nt++) {
            const int r0 = rowBase + mW + mt * 16 + (lane >> 2);
            const int c0 = colBase + nW + nt * 8 + 2 * (lane & 3);
            *(float2*)&C[(size_t)r0 * EMBED + c0] =
                make_float2(acc[mt][nt][0], acc[mt][nt][1]);
            *(float2*)&C[(size_t)(r0 + 8) * EMBED + c0] =
                make_float2(acc[mt][nt][2], acc[mt][nt][3]);
        }
    }
}

// ---------------------------------------------------------------------------
extern "C" void kernel_launch(void* const* d_in, const int* in_sizes, int n_in,
                              void* d_out, int out_size)
{
    const float* x  = (const float*)d_in[0];
    const float* Wq = (const float*)d_in[1];
    const float* bq = (const float*)d_in[2];
    const float* Wk = (const float*)d_in[3];
    const float* bk = (const float*)d_in[4];
    const float* Wv = (const float*)d_in[5];
    const float* bv = (const float*)d_in[6];

    float* out = (float*)d_out;
    float* wts = out + (size_t)MTOT * EMBED;

    cudaFuncSetAttribute(qkv_k,    cudaFuncAttributeMaxDynamicSharedMemorySize, SMEM_DYN);
    cudaFuncSetAttribute(scores_k, cudaFuncAttributeMaxDynamicSharedMemorySize, SMEM_DYN);
    cudaFuncSetAttribute(av_k,     cudaFuncAttributeMaxDynamicSharedMemorySize, SMEM_DYN);

    __nv_bfloat16 *xh, *xl, *Wh, *Wl;
    cudaGetSymbolAddress((void**)&xh, g_xh);
    cudaGetSymbolAddress((void**)&xl, g_xl);
    cudaGetSymbolAddress((void**)&Wh, g_Wh);
    cudaGetSymbolAddress((void**)&Wl, g_Wl);

    const int nx4 = MTOT * EMBED / 4;
    const int nw4 = EMBED * EMBED / 4;
    split_k<<<(nx4 + 255) / 256, 256>>>(x, xh, xl, nx4);
    split_k<<<(nw4 + 255) / 256, 256>>>(Wq, Wh,               Wl,               nw4);
    split_k<<<(nw4 + 255) / 256, 256>>>(Wk, Wh + nw4 * 4,     Wl + nw4 * 4,     nw4);
    split_k<<<(nw4 + 255) / 256, 256>>>(Wv, Wh + 2 * nw4 * 4, Wl + 2 * nw4 * 4, nw4);

    qkv_k<<<dim3(EMBED / 128, MTOT / 128, 3), NTHREADS, SMEM_DYN>>>(bq, bk, bv);
    scores_k<<<dim3(SEQ / 128, SEQ / 128, BATCH), NTHREADS, SMEM_DYN>>>(wts);
    softmax_k<<<dim3(MTOT), dim3(256)>>>(wts);
    av_k<<<dim3(EMBED / 128, SEQ / 128, BATCH), NTHREADS, SMEM_DYN>>>(out);
}